// round 12
// baseline (speedup 1.0000x reference)
#include <cuda_runtime.h>

// Problem constants
#define N_TOT 8192
#define F_DIM 128
#define FP    (F_DIM / 2)          // 64 f-pairs
#define NFP   (N_TOT * FP)         // 524,288 threads, each handles (f, f+1)

// out[n,a,b,f,uv] = 0.75*(x[n,a,f,u]*y[n,b,f,v] + x[n,b,f,u]*y[n,a,f,v])
//                 - 0.5*z[n,f,uv]*(a==b)
// x: [N,3,F,2]  y: [N,3,F,2]  z: [N,F,4]  out: [N,3,3,F,4]
//
// Best-of-both configuration at the measured B300 mixed R/W DRAM floor
// (218 MB/replay @ ~5.85 TB/s sustained):
//  - f-pair per thread, LDG.128 input loads, one 256-bit store per tile
//    (best profiled in-window time of all variants: ~30.4 us)
//  - streaming cache ops on both sides (.nc loads, .cs stores): zero reuse
//  - 256-thread blocks, all 7 loads front-batched for MLP

__device__ __forceinline__ void stg256cs(float4* p, const float4& v0, const float4& v1) {
    asm volatile(
        "st.global.cs.v8.f32 [%0], {%1, %2, %3, %4, %5, %6, %7, %8};"
        :: "l"(p),
           "f"(v0.x), "f"(v0.y), "f"(v0.z), "f"(v0.w),
           "f"(v1.x), "f"(v1.y), "f"(v1.z), "f"(v1.w)
        : "memory");
}

__device__ __forceinline__ void ldg256(const float4* p, float4& v0, float4& v1) {
    asm volatile(
        "ld.global.nc.v8.f32 {%0, %1, %2, %3, %4, %5, %6, %7}, [%8];"
        : "=f"(v0.x), "=f"(v0.y), "=f"(v0.z), "=f"(v0.w),
          "=f"(v1.x), "=f"(v1.y), "=f"(v1.z), "=f"(v1.w)
        : "l"(p));
}

__global__ __launch_bounds__(256) void tp_block2_kernel(
    const float4* __restrict__ x,   // viewed as [N,3,FP] float4
    const float4* __restrict__ y,   // viewed as [N,3,FP] float4
    const float4* __restrict__ z,   // viewed as [N,F] float4
    float4* __restrict__ out)       // viewed as [N,3,3,F] float4
{
    int idx = blockIdx.x * blockDim.x + threadIdx.x;
    if (idx >= NFP) return;
    int n  = idx / FP;
    int fp = idx - n * FP;          // f-pair index; f0 = 2*fp, f1 = 2*fp+1

    // Front-batch all loads: 6x LDG.128 + 1x LDG.256.
    int base = (n * 3) * FP + fp;   // float4 index of x[n,0,2fp..2fp+1,:]
    float4 xa[3], yb[3];
    xa[0] = __ldcs(&x[base]);
    xa[1] = __ldcs(&x[base + FP]);
    xa[2] = __ldcs(&x[base + 2 * FP]);
    yb[0] = __ldcs(&y[base]);
    yb[1] = __ldcs(&y[base + FP]);
    yb[2] = __ldcs(&y[base + 2 * FP]);
    float4 z0, z1;
    ldg256(&z[n * F_DIM + 2 * fp], z0, z1);

    const float c1 = 0.75f;         // NORM_112
    const float c2 = 0.5f;          // 0.75 * 2/3

    // Pre-scale z (diagonal term).
    float4 zc0, zc1;
    zc0.x = c2 * z0.x; zc0.y = c2 * z0.y; zc0.z = c2 * z0.z; zc0.w = c2 * z0.w;
    zc1.x = c2 * z1.x; zc1.y = c2 * z1.y; zc1.z = c2 * z1.z; zc1.w = c2 * z1.w;

    // xa[a] = (f0.u0, f0.u1, f1.u0, f1.u1); same layout for yb.
    int obase = (n * 9) * F_DIM + 2 * fp;   // float4 index of out[n,0,0,2fp]
#pragma unroll
    for (int a = 0; a < 3; a++) {
#pragma unroll
        for (int b = 0; b < 3; b++) {
            float4 v0, v1;
            // f0: uses .x/.y halves
            v0.x = c1 * (xa[a].x * yb[b].x + xa[b].x * yb[a].x);
            v0.y = c1 * (xa[a].x * yb[b].y + xa[b].x * yb[a].y);
            v0.z = c1 * (xa[a].y * yb[b].x + xa[b].y * yb[a].x);
            v0.w = c1 * (xa[a].y * yb[b].y + xa[b].y * yb[a].y);
            // f1: uses .z/.w halves
            v1.x = c1 * (xa[a].z * yb[b].z + xa[b].z * yb[a].z);
            v1.y = c1 * (xa[a].z * yb[b].w + xa[b].z * yb[a].w);
            v1.z = c1 * (xa[a].w * yb[b].z + xa[b].w * yb[a].z);
            v1.w = c1 * (xa[a].w * yb[b].w + xa[b].w * yb[a].w);
            if (a == b) {
                v0.x -= zc0.x; v0.y -= zc0.y; v0.z -= zc0.z; v0.w -= zc0.w;
                v1.x -= zc1.x; v1.y -= zc1.y; v1.z -= zc1.z; v1.w -= zc1.w;
            }
            stg256cs(&out[obase + (a * 3 + b) * F_DIM], v0, v1);
        }
    }
}

extern "C" void kernel_launch(void* const* d_in, const int* in_sizes, int n_in,
                              void* d_out, int out_size) {
    const float4* x = (const float4*)d_in[0];
    const float4* y = (const float4*)d_in[1];
    const float4* z = (const float4*)d_in[2];
    // d_in[3] is eye (identity) — value known, not needed.
    float4* out = (float4*)d_out;

    const int threads = 256;
    const int blocks = (NFP + threads - 1) / threads;
    tp_block2_kernel<<<blocks, threads>>>(x, y, z, out);
}

// round 13
// speedup vs baseline: 1.0060x; 1.0060x over previous
#include <cuda_runtime.h>

// Problem constants
#define N_TOT 8192
#define F_DIM 128
#define NF (N_TOT * F_DIM)   // 1,048,576 (n,f) pairs

// out[n,a,b,f,uv] = 0.75*(x[n,a,f,u]*y[n,b,f,v] + x[n,b,f,u]*y[n,a,f,v])
//                 - 0.5*z[n,f,uv]*(a==b)
// x: [N,3,F,2]  y: [N,3,F,2]  z: [N,F,4]  out: [N,3,3,F,4]
//
// FINAL (best measured: 37.344 us, reproduced twice).
// Pure streaming kernel at the B300 mixed read/write DRAM floor:
// 218 MB mandatory once-touched traffic @ ~5.85 TB/s sustained (73% of spec
// on a 31%R/69%W mix). Twelve rounds of variants — cache-policy permutations,
// 64/128/256-bit accesses, f/n batching, symmetry-reduced FLOPs, persistent
// single-wave grid, TMA bulk stores — all confirmed this floor.
//  - one thread per (n,f): every access perfectly coalesced
//  - 7 front-batched loads (max MLP), 9 float4 stores
//  - evict-first on both streams (zero reuse), regs=32, occ ~78%
__global__ __launch_bounds__(256) void tp_block2_kernel(
    const float2* __restrict__ x,   // viewed as [N,3,F] float2
    const float2* __restrict__ y,   // viewed as [N,3,F] float2
    const float4* __restrict__ z,   // viewed as [N,F] float4
    float4* __restrict__ out)       // viewed as [N,3,3,F] float4
{
    int idx = blockIdx.x * blockDim.x + threadIdx.x;
    if (idx >= NF) return;
    int n = idx >> 7;               // idx / 128
    int f = idx & (F_DIM - 1);      // idx % 128

    // Front-batch all 7 loads for max MLP.
    int base = (n * 3) * F_DIM + f;          // float2 index of [n,0,f]
    float2 xa0 = __ldcs(&x[base]);
    float2 xa1 = __ldcs(&x[base + F_DIM]);
    float2 xa2 = __ldcs(&x[base + 2 * F_DIM]);
    float2 yb0 = __ldcs(&y[base]);
    float2 yb1 = __ldcs(&y[base + F_DIM]);
    float2 yb2 = __ldcs(&y[base + 2 * F_DIM]);
    float4 zv  = __ldcs(&z[idx]);

    float2 xa[3] = {xa0, xa1, xa2};
    float2 yb[3] = {yb0, yb1, yb2};

    const float c1 = 0.75f;                  // NORM_112
    const float c2 = 0.5f;                   // 0.75 * 2/3

    // Pre-scale z once (diagonal term).
    float4 zc;
    zc.x = c2 * zv.x; zc.y = c2 * zv.y; zc.z = c2 * zv.z; zc.w = c2 * zv.w;

    int obase = (n * 9) * F_DIM + f;         // float4 index of out[n,0,0,f]
#pragma unroll
    for (int a = 0; a < 3; a++) {
#pragma unroll
        for (int b = 0; b < 3; b++) {
            float4 v;
            // uv order: (u,v) = (0,0),(0,1),(1,0),(1,1)
            v.x = c1 * (xa[a].x * yb[b].x + xa[b].x * yb[a].x);
            v.y = c1 * (xa[a].x * yb[b].y + xa[b].x * yb[a].y);
            v.z = c1 * (xa[a].y * yb[b].x + xa[b].y * yb[a].x);
            v.w = c1 * (xa[a].y * yb[b].y + xa[b].y * yb[a].y);
            if (a == b) {
                v.x -= zc.x;
                v.y -= zc.y;
                v.z -= zc.z;
                v.w -= zc.w;
            }
            __stcs(&out[obase + (a * 3 + b) * F_DIM], v);
        }
    }
}

extern "C" void kernel_launch(void* const* d_in, const int* in_sizes, int n_in,
                              void* d_out, int out_size) {
    const float2* x = (const float2*)d_in[0];
    const float2* y = (const float2*)d_in[1];
    const float4* z = (const float4*)d_in[2];
    // d_in[3] is eye (identity) — value known, not needed.
    float4* out = (float4*)d_out;

    const int threads = 256;
    const int blocks = (NF + threads - 1) / threads;
    tp_block2_kernel<<<blocks, threads>>>(x, y, z, out);
}

// round 14
// speedup vs baseline: 1.0069x; 1.0009x over previous
#include <cuda_runtime.h>

// Problem constants
#define N_TOT 8192
#define F_DIM 128
#define NF (N_TOT * F_DIM)   // 1,048,576 (n,f) pairs

// out[n,a,b,f,uv] = 0.75*(x[n,a,f,u]*y[n,b,f,v] + x[n,b,f,u]*y[n,a,f,v])
//                 - 0.5*z[n,f,uv]*(a==b)
// x: [N,3,F,2]  y: [N,3,F,2]  z: [N,F,4]  out: [N,3,3,F,4]
//
// Streaming kernel at the B300 mixed read/write DRAM floor (218 MB mandatory
// once-touched traffic @ ~5.85 TB/s sustained = 73% of spec, 31%R/69%W mix).
// This round: identical memory structure to the 37.344 us best, with
// 512-thread blocks (2048 CTAs) to halve CTA launch/retire churn — the last
// unexplored launch-shape knob.
//  - one thread per (n,f): every access perfectly coalesced
//  - 7 front-batched loads (max MLP), 9 float4 stores
//  - evict-first on both streams (zero reuse), regs=32
__global__ __launch_bounds__(512) void tp_block2_kernel(
    const float2* __restrict__ x,   // viewed as [N,3,F] float2
    const float2* __restrict__ y,   // viewed as [N,3,F] float2
    const float4* __restrict__ z,   // viewed as [N,F] float4
    float4* __restrict__ out)       // viewed as [N,3,3,F] float4
{
    int idx = blockIdx.x * blockDim.x + threadIdx.x;
    if (idx >= NF) return;
    int n = idx >> 7;               // idx / 128
    int f = idx & (F_DIM - 1);      // idx % 128

    // Front-batch all 7 loads for max MLP.
    int base = (n * 3) * F_DIM + f;          // float2 index of [n,0,f]
    float2 xa0 = __ldcs(&x[base]);
    float2 xa1 = __ldcs(&x[base + F_DIM]);
    float2 xa2 = __ldcs(&x[base + 2 * F_DIM]);
    float2 yb0 = __ldcs(&y[base]);
    float2 yb1 = __ldcs(&y[base + F_DIM]);
    float2 yb2 = __ldcs(&y[base + 2 * F_DIM]);
    float4 zv  = __ldcs(&z[idx]);

    float2 xa[3] = {xa0, xa1, xa2};
    float2 yb[3] = {yb0, yb1, yb2};

    const float c1 = 0.75f;                  // NORM_112
    const float c2 = 0.5f;                   // 0.75 * 2/3

    // Pre-scale z once (diagonal term).
    float4 zc;
    zc.x = c2 * zv.x; zc.y = c2 * zv.y; zc.z = c2 * zv.z; zc.w = c2 * zv.w;

    int obase = (n * 9) * F_DIM + f;         // float4 index of out[n,0,0,f]
#pragma unroll
    for (int a = 0; a < 3; a++) {
#pragma unroll
        for (int b = 0; b < 3; b++) {
            float4 v;
            // uv order: (u,v) = (0,0),(0,1),(1,0),(1,1)
            v.x = c1 * (xa[a].x * yb[b].x + xa[b].x * yb[a].x);
            v.y = c1 * (xa[a].x * yb[b].y + xa[b].x * yb[a].y);
            v.z = c1 * (xa[a].y * yb[b].x + xa[b].y * yb[a].x);
            v.w = c1 * (xa[a].y * yb[b].y + xa[b].y * yb[a].y);
            if (a == b) {
                v.x -= zc.x;
                v.y -= zc.y;
                v.z -= zc.z;
                v.w -= zc.w;
            }
            __stcs(&out[obase + (a * 3 + b) * F_DIM], v);
        }
    }
}

extern "C" void kernel_launch(void* const* d_in, const int* in_sizes, int n_in,
                              void* d_out, int out_size) {
    const float2* x = (const float2*)d_in[0];
    const float2* y = (const float2*)d_in[1];
    const float4* z = (const float4*)d_in[2];
    // d_in[3] is eye (identity) — value known, not needed.
    float4* out = (float4*)d_out;

    const int threads = 512;
    const int blocks = (NF + threads - 1) / threads;
    tp_block2_kernel<<<blocks, threads>>>(x, y, z, out);
}